// round 8
// baseline (speedup 1.0000x reference)
#include <cuda_runtime.h>

#define Bc  4
#define LXc 384
#define LYc 384
#define Hc  256
#define Fc  512

typedef unsigned long long ull;

// scratch (allocation-free rule: __device__ globals)
__device__ float g_Xp[Bc * LXc * Hc];   // x @ Wm^T
__device__ float g_Yp[Bc * LYc * Hc];   // y @ Wm^T
__device__ float g_S [Bc * LYc * LXc];  // scores -> softmax'd in place

__device__ __forceinline__ float tanh_fast(float x) {
    float r; asm("tanh.approx.f32 %0, %1;" : "=f"(r) : "f"(x)); return r;
}
__device__ __forceinline__ float ex2_fast(float x) {
    float r; asm("ex2.approx.f32 %0, %1;" : "=f"(r) : "f"(x)); return r;
}
__device__ __forceinline__ ull pack2(float lo, float hi) {
    ull r; asm("mov.b64 %0, {%1, %2};" : "=l"(r) : "f"(lo), "f"(hi)); return r;
}
__device__ __forceinline__ float2 unpack2(ull v) {
    float lo, hi; asm("mov.b64 {%0, %1}, %2;" : "=f"(lo), "=f"(hi) : "l"(v));
    return make_float2(lo, hi);
}
__device__ __forceinline__ ull fma2(ull a, ull b, ull c) {
    ull r; asm("fma.rn.f32x2 %0, %1, %2, %3;" : "=l"(r) : "l"(a), "l"(b), "l"(c));
    return r;
}

// ---------------------------------------------------------------------------
// Kernel 1: Out[r,h] = sum_f In[r,f] * W[h,f]   (NT GEMM, both K-major)
// M=1536, N=256, K=512.  64x64 tile, 128 threads, 4x8 micro-tile,
// BK=16 double-buffered.  Per kk: 3 LDS.128 + 4 packs -> 16 FFMA2
// (32 fma-cyc > 29-cyc LDS latency: single-warp latency tolerant).
// grid (24, 4, 2) = 192 blocks.
// ---------------------------------------------------------------------------
__global__ __launch_bounds__(128) void proj_kernel(
    const float* __restrict__ xin, const float* __restrict__ yin,
    const float* __restrict__ W)
{
    const float* In  = blockIdx.z ? yin  : xin;
    float*       Out = blockIdx.z ? g_Yp : g_Xp;

    __shared__ float As[2][16][68];   // [k][m(64)]  272B row stride (16B-aligned)
    __shared__ float Bs[2][16][68];   // [k][n(64)]

    const int tid = threadIdx.x;
    const int r0  = blockIdx.x * 64;
    const int h0  = blockIdx.y * 64;

    const int lr = tid >> 1;            // 0..63 row for loads
    const int ko = (tid & 1) * 8;       // k sub (8 floats)

    const int tx = tid & 7;             // n micro-col (8 cols)
    const int ty = tid >> 3;            // m micro-row (0..15, 4 rows)

    const float* pA = &In[(r0 + lr) * Fc + ko];
    const float* pB = &W [(h0 + lr) * Fc + ko];

    ull acc[4][4] = {};

    // prologue: chunk 0 -> buf 0
    {
        float4 a0 = *(const float4*)pA;
        float4 a1 = *(const float4*)(pA + 4);
        float4 b0 = *(const float4*)pB;
        float4 b1 = *(const float4*)(pB + 4);
        As[0][ko + 0][lr] = a0.x; As[0][ko + 1][lr] = a0.y;
        As[0][ko + 2][lr] = a0.z; As[0][ko + 3][lr] = a0.w;
        As[0][ko + 4][lr] = a1.x; As[0][ko + 5][lr] = a1.y;
        As[0][ko + 6][lr] = a1.z; As[0][ko + 7][lr] = a1.w;
        Bs[0][ko + 0][lr] = b0.x; Bs[0][ko + 1][lr] = b0.y;
        Bs[0][ko + 2][lr] = b0.z; Bs[0][ko + 3][lr] = b0.w;
        Bs[0][ko + 4][lr] = b1.x; Bs[0][ko + 5][lr] = b1.y;
        Bs[0][ko + 6][lr] = b1.z; Bs[0][ko + 7][lr] = b1.w;
    }
    __syncthreads();

    int buf = 0;
    for (int k0 = 16; k0 <= Fc; k0 += 16) {
        float4 a0, a1, b0, b1;
        if (k0 < Fc) {
            a0 = *(const float4*)(pA + k0);
            a1 = *(const float4*)(pA + k0 + 4);
            b0 = *(const float4*)(pB + k0);
            b1 = *(const float4*)(pB + k0 + 4);
        }
        #pragma unroll
        for (int kk = 0; kk < 16; kk++) {
            float4 a = *(const float4*)&As[buf][kk][ty * 4];
            ulonglong2 B01 = *(const ulonglong2*)&Bs[buf][kk][tx * 8];
            ulonglong2 B23 = *(const ulonglong2*)&Bs[buf][kk][tx * 8 + 4];
            ull ax = pack2(a.x, a.x), ay = pack2(a.y, a.y);
            ull az = pack2(a.z, a.z), aw = pack2(a.w, a.w);
            acc[0][0] = fma2(ax, B01.x, acc[0][0]);
            acc[0][1] = fma2(ax, B01.y, acc[0][1]);
            acc[0][2] = fma2(ax, B23.x, acc[0][2]);
            acc[0][3] = fma2(ax, B23.y, acc[0][3]);
            acc[1][0] = fma2(ay, B01.x, acc[1][0]);
            acc[1][1] = fma2(ay, B01.y, acc[1][1]);
            acc[1][2] = fma2(ay, B23.x, acc[1][2]);
            acc[1][3] = fma2(ay, B23.y, acc[1][3]);
            acc[2][0] = fma2(az, B01.x, acc[2][0]);
            acc[2][1] = fma2(az, B01.y, acc[2][1]);
            acc[2][2] = fma2(az, B23.x, acc[2][2]);
            acc[2][3] = fma2(az, B23.y, acc[2][3]);
            acc[3][0] = fma2(aw, B01.x, acc[3][0]);
            acc[3][1] = fma2(aw, B01.y, acc[3][1]);
            acc[3][2] = fma2(aw, B23.x, acc[3][2]);
            acc[3][3] = fma2(aw, B23.y, acc[3][3]);
        }
        if (k0 < Fc) {
            int nb = buf ^ 1;
            As[nb][ko + 0][lr] = a0.x; As[nb][ko + 1][lr] = a0.y;
            As[nb][ko + 2][lr] = a0.z; As[nb][ko + 3][lr] = a0.w;
            As[nb][ko + 4][lr] = a1.x; As[nb][ko + 5][lr] = a1.y;
            As[nb][ko + 6][lr] = a1.z; As[nb][ko + 7][lr] = a1.w;
            Bs[nb][ko + 0][lr] = b0.x; Bs[nb][ko + 1][lr] = b0.y;
            Bs[nb][ko + 2][lr] = b0.z; Bs[nb][ko + 3][lr] = b0.w;
            Bs[nb][ko + 4][lr] = b1.x; Bs[nb][ko + 5][lr] = b1.y;
            Bs[nb][ko + 6][lr] = b1.z; Bs[nb][ko + 7][lr] = b1.w;
            __syncthreads();
            buf = nb;
        }
    }

    #pragma unroll
    for (int i = 0; i < 4; i++) {
        float2 p0 = unpack2(acc[i][0]);
        float2 p1 = unpack2(acc[i][1]);
        float2 p2 = unpack2(acc[i][2]);
        float2 p3 = unpack2(acc[i][3]);
        float* po = &Out[(r0 + ty * 4 + i) * Hc + h0 + tx * 8];
        *(float4*)po       = make_float4(p0.x, p0.y, p1.x, p1.y);
        *(float4*)(po + 4) = make_float4(p2.x, p2.y, p3.x, p3.y);
    }
}

// ---------------------------------------------------------------------------
// Kernel 2: GEMM-shaped tanh-score (MUFU-bound, at its floor — unchanged).
// S[b,y,l] = sum_h vm[h] * tanh(Xp[b,l,h] - Yp[b,y,h])
// ---------------------------------------------------------------------------
__global__ __launch_bounds__(256) void score_tile_kernel(const float* __restrict__ vm)
{
    const int b  = blockIdx.z;
    const int y0 = blockIdx.y * 64;
    const int l0 = blockIdx.x * 64;

    __shared__ float Ys[16][68];
    __shared__ float Xs[16][68];
    __shared__ float Vs[Hc];

    const int tid = threadIdx.x;
    for (int i = tid; i < Hc; i += 256) Vs[i] = vm[i];

    const int lrow = tid >> 2;
    const int f4   = (tid & 3) * 4;
    const int tx   = tid & 15;
    const int ty   = tid >> 4;

    const float* Yb = g_Yp + (b * LYc + y0) * Hc;
    const float* Xb = g_Xp + (b * LXc + l0) * Hc;

    float acc[4][4] = {};

    for (int k0 = 0; k0 < Hc; k0 += 16) {
        float4 av = *(const float4*)&Yb[lrow * Hc + k0 + f4];
        float4 bv = *(const float4*)&Xb[lrow * Hc + k0 + f4];
        __syncthreads();
        Ys[f4 + 0][lrow] = av.x; Ys[f4 + 1][lrow] = av.y;
        Ys[f4 + 2][lrow] = av.z; Ys[f4 + 3][lrow] = av.w;
        Xs[f4 + 0][lrow] = bv.x; Xs[f4 + 1][lrow] = bv.y;
        Xs[f4 + 2][lrow] = bv.z; Xs[f4 + 3][lrow] = bv.w;
        __syncthreads();

        #pragma unroll
        for (int kk = 0; kk < 16; kk++) {
            const float v = Vs[k0 + kk];
            float4 yv = *(const float4*)&Ys[kk][ty * 4];
            float4 xv = *(const float4*)&Xs[kk][tx * 4];
            float t00 = tanh_fast(xv.x - yv.x);
            float t01 = tanh_fast(xv.y - yv.x);
            float t02 = tanh_fast(xv.z - yv.x);
            float t03 = tanh_fast(xv.w - yv.x);
            float t10 = tanh_fast(xv.x - yv.y);
            float t11 = tanh_fast(xv.y - yv.y);
            float t12 = tanh_fast(xv.z - yv.y);
            float t13 = tanh_fast(xv.w - yv.y);
            float t20 = tanh_fast(xv.x - yv.z);
            float t21 = tanh_fast(xv.y - yv.z);
            float t22 = tanh_fast(xv.z - yv.z);
            float t23 = tanh_fast(xv.w - yv.z);
            float t30 = tanh_fast(xv.x - yv.w);
            float t31 = tanh_fast(xv.y - yv.w);
            float t32 = tanh_fast(xv.z - yv.w);
            float t33 = tanh_fast(xv.w - yv.w);
            acc[0][0] = fmaf(v, t00, acc[0][0]);
            acc[0][1] = fmaf(v, t01, acc[0][1]);
            acc[0][2] = fmaf(v, t02, acc[0][2]);
            acc[0][3] = fmaf(v, t03, acc[0][3]);
            acc[1][0] = fmaf(v, t10, acc[1][0]);
            acc[1][1] = fmaf(v, t11, acc[1][1]);
            acc[1][2] = fmaf(v, t12, acc[1][2]);
            acc[1][3] = fmaf(v, t13, acc[1][3]);
            acc[2][0] = fmaf(v, t20, acc[2][0]);
            acc[2][1] = fmaf(v, t21, acc[2][1]);
            acc[2][2] = fmaf(v, t22, acc[2][2]);
            acc[2][3] = fmaf(v, t23, acc[2][3]);
            acc[3][0] = fmaf(v, t30, acc[3][0]);
            acc[3][1] = fmaf(v, t31, acc[3][1]);
            acc[3][2] = fmaf(v, t32, acc[3][2]);
            acc[3][3] = fmaf(v, t33, acc[3][3]);
        }
    }

    float* Sb = g_S + (b * LYc + y0) * LXc + l0;
    #pragma unroll
    for (int i = 0; i < 4; i++) {
        float4 st = make_float4(acc[i][0], acc[i][1], acc[i][2], acc[i][3]);
        *(float4*)&Sb[(ty * 4 + i) * LXc + tx * 4] = st;
    }
}

// ---------------------------------------------------------------------------
// Kernel 3a: softmax over l, in place on g_S. Warp per row.
// ---------------------------------------------------------------------------
__global__ __launch_bounds__(256) void softmax_kernel()
{
    const int b    = blockIdx.y;
    const int y    = blockIdx.x * 8 + (threadIdx.x >> 5);
    const int lane = threadIdx.x & 31;

    float* Srow = g_S + (b * LYc + y) * LXc;
    float v[12];
    float mx = -1e30f;
    #pragma unroll
    for (int j = 0; j < 12; j++) {
        v[j] = Srow[lane + 32 * j];
        mx = fmaxf(mx, v[j]);
    }
    #pragma unroll
    for (int o = 16; o; o >>= 1)
        mx = fmaxf(mx, __shfl_xor_sync(0xffffffffu, mx, o));
    float sum = 0.f;
    #pragma unroll
    for (int j = 0; j < 12; j++) {
        v[j] = ex2_fast((v[j] - mx) * 1.4426950408889634f);
        sum += v[j];
    }
    #pragma unroll
    for (int o = 16; o; o >>= 1)
        sum += __shfl_xor_sync(0xffffffffu, sum, o);
    float inv = 1.0f / sum;
    #pragma unroll
    for (int j = 0; j < 12; j++)
        Srow[lane + 32 * j] = v[j] * inv;
}

// ---------------------------------------------------------------------------
// Kernel 3b: qtm[b,y,f] = sum_l A[b,y,l] * x[b,l,f]
// Per-batch GEMM M=384(y), N=512(f), K=384(l).  64x64 tile, 128 threads,
// 4x8 micro-tile, BK=16 double-buffered.  grid (8, 6, 4) = 192 blocks.
// ---------------------------------------------------------------------------
__global__ __launch_bounds__(128) void outgemm_kernel(
    const float* __restrict__ x, float* __restrict__ out)
{
    const int b  = blockIdx.z;
    const int f0 = blockIdx.x * 64;
    const int y0 = blockIdx.y * 64;

    __shared__ float As[2][16][68];   // [k(l)][y(64)]
    __shared__ float Xs[2][16][68];   // [k(l)][f(64)]

    const int tid = threadIdx.x;

    const int lrA = tid >> 1;           // 0..63 (y row for A load)
    const int kA  = (tid & 1) * 8;      // l sub for A load (8 floats)
    const int lX  = tid >> 3;           // 0..15 (l row for X load)
    const int fX  = (tid & 7) * 8;      // f sub for X load (8 floats)

    const int tx = tid & 7;             // f micro-col (8)
    const int ty = tid >> 3;            // y micro-row (0..15, 4 rows)

    const float* pA = g_S + (b * LYc + y0 + lrA) * LXc + kA;
    const float* pX = x + b * LXc * Fc + lX * Fc + f0 + fX;

    ull acc[4][4] = {};

    {
        float4 a0 = *(const float4*)pA;
        float4 a1 = *(const float4*)(pA + 4);
        float4 x0 = *(const float4*)pX;
        float4 x1 = *(const float4*)(pX + 4);
        As[0][kA + 0][lrA] = a0.x; As[0][kA + 1][lrA] = a0.y;
        As[0][kA + 2][lrA] = a0.z; As[0][kA + 3][lrA] = a0.w;
        As[0][kA + 4][lrA] = a1.x; As[0][kA + 5][lrA] = a1.y;
        As[0][kA + 6][lrA] = a1.z; As[0][kA + 7][lrA] = a1.w;
        *(float4*)&Xs[0][lX][fX]     = x0;
        *(float4*)&Xs[0][lX][fX + 4] = x1;
    }
    __syncthreads();

    int buf = 0;
    for (int k0 = 16; k0 <= LXc; k0 += 16) {
        float4 a0, a1, x0, x1;
        if (k0 < LXc) {
            a0 = *(const float4*)(pA + k0);
            a1 = *(const float4*)(pA + k0 + 4);
            x0 = *(const float4*)(pX + k0 * Fc);
            x1 = *(const float4*)(pX + k0 * Fc + 4);
        }
        #pragma unroll
        for (int kk = 0; kk < 16; kk++) {
            float4 a = *(const float4*)&As[buf][kk][ty * 4];
            ulonglong2 B01 = *(const ulonglong2*)&Xs[buf][kk][tx * 8];
            ulonglong2 B23 = *(const ulonglong2*)&Xs[buf][kk][tx * 8 + 4];
            ull ax = pack2(a.x, a.x), ay = pack2(a.y, a.y);
            ull az = pack2(a.z, a.z), aw = pack2(a.w, a.w);
            acc[0][0] = fma2(ax, B01.x, acc[0][0]);
            acc[0][1] = fma2(ax, B01.y, acc[0][1]);
            acc[0][2] = fma2(ax, B23.x, acc[0][2]);
            acc[0][3] = fma2(ax, B23.y, acc[0][3]);
            acc[1][0] = fma2(ay, B01.x, acc[1][0]);
            acc[1][1] = fma2(ay, B01.y, acc[1][1]);
            acc[1][2] = fma2(ay, B23.x, acc[1][2]);
            acc[1][3] = fma2(ay, B23.y, acc[1][3]);
            acc[2][0] = fma2(az, B01.x, acc[2][0]);
            acc[2][1] = fma2(az, B01.y, acc[2][1]);
            acc[2][2] = fma2(az, B23.x, acc[2][2]);
            acc[2][3] = fma2(az, B23.y, acc[2][3]);
            acc[3][0] = fma2(aw, B01.x, acc[3][0]);
            acc[3][1] = fma2(aw, B01.y, acc[3][1]);
            acc[3][2] = fma2(aw, B23.x, acc[3][2]);
            acc[3][3] = fma2(aw, B23.y, acc[3][3]);
        }
        if (k0 < LXc) {
            int nb = buf ^ 1;
            As[nb][kA + 0][lrA] = a0.x; As[nb][kA + 1][lrA] = a0.y;
            As[nb][kA + 2][lrA] = a0.z; As[nb][kA + 3][lrA] = a0.w;
            As[nb][kA + 4][lrA] = a1.x; As[nb][kA + 5][lrA] = a1.y;
            As[nb][kA + 6][lrA] = a1.z; As[nb][kA + 7][lrA] = a1.w;
            *(float4*)&Xs[nb][lX][fX]     = x0;
            *(float4*)&Xs[nb][lX][fX + 4] = x1;
            __syncthreads();
            buf = nb;
        }
    }

    #pragma unroll
    for (int i = 0; i < 4; i++) {
        float2 p0 = unpack2(acc[i][0]);
        float2 p1 = unpack2(acc[i][1]);
        float2 p2 = unpack2(acc[i][2]);
        float2 p3 = unpack2(acc[i][3]);
        float* po = &out[(b * LYc + y0 + ty * 4 + i) * Fc + f0 + tx * 8];
        *(float4*)po       = make_float4(p0.x, p0.y, p1.x, p1.y);
        *(float4*)(po + 4) = make_float4(p2.x, p2.y, p3.x, p3.y);
    }
}

// ---------------------------------------------------------------------------
extern "C" void kernel_launch(void* const* d_in, const int* in_sizes, int n_in,
                              void* d_out, int out_size)
{
    const float* x  = (const float*)d_in[0];
    const float* y  = (const float*)d_in[1];
    const float* Wm = (const float*)d_in[2];
    const float* vm = (const float*)d_in[3];
    float* out = (float*)d_out;

    proj_kernel      <<<dim3(LXc * Bc / 64, Hc / 64, 2), 128>>>(x, y, Wm);
    score_tile_kernel<<<dim3(LXc / 64, LYc / 64, Bc), 256>>>(vm);
    softmax_kernel   <<<dim3(LYc / 8, Bc), 256>>>();
    outgemm_kernel   <<<dim3(Fc / 64, LYc / 64, Bc), 128>>>(x, out);
}

// round 9
// speedup vs baseline: 1.2365x; 1.2365x over previous
#include <cuda_runtime.h>

#define Bc  4
#define LXc 384
#define LYc 384
#define Hc  256
#define Fc  512

typedef unsigned long long ull;

// scratch (allocation-free rule: __device__ globals)
__device__ float g_Xp[Bc * LXc * Hc];   // x @ Wm^T
__device__ float g_Yp[Bc * LYc * Hc];   // y @ Wm^T
__device__ float g_S [Bc * LYc * LXc];  // scores -> softmax'd in place

__device__ __forceinline__ float tanh_fast(float x) {
    float r; asm("tanh.approx.f32 %0, %1;" : "=f"(r) : "f"(x)); return r;
}
__device__ __forceinline__ float ex2_fast(float x) {
    float r; asm("ex2.approx.f32 %0, %1;" : "=f"(r) : "f"(x)); return r;
}
__device__ __forceinline__ ull pack2(float lo, float hi) {
    ull r; asm("mov.b64 %0, {%1, %2};" : "=l"(r) : "f"(lo), "f"(hi)); return r;
}
__device__ __forceinline__ float2 unpack2(ull v) {
    float lo, hi; asm("mov.b64 {%0, %1}, %2;" : "=f"(lo), "=f"(hi) : "l"(v));
    return make_float2(lo, hi);
}
__device__ __forceinline__ ull fma2(ull a, ull b, ull c) {
    ull r; asm("fma.rn.f32x2 %0, %1, %2, %3;" : "=l"(r) : "l"(a), "l"(b), "l"(c));
    return r;
}

// ---------------------------------------------------------------------------
// Kernel 1: Out[r,h] = sum_f In[r,f] * W[h,f]   (NT GEMM, both K-major)
// M=1536, N=256, K=512.  32x64 tile, 128 threads, 4x4 micro (R5 tiling),
// BK=32 double-buffered (16 chunks, half the barrier/LDG overhead of BK=16).
// grid (48, 4, 2) = 384 blocks.
// ---------------------------------------------------------------------------
__global__ __launch_bounds__(128) void proj_kernel(
    const float* __restrict__ xin, const float* __restrict__ yin,
    const float* __restrict__ W)
{
    const float* In  = blockIdx.z ? yin  : xin;
    float*       Out = blockIdx.z ? g_Yp : g_Xp;

    __shared__ float As[2][32][36];   // [k][m(32)]  144B stride (16B-aligned)
    __shared__ float Bs[2][32][68];   // [k][n(64)]  272B stride (16B-aligned)

    const int tid = threadIdx.x;
    const int r0  = blockIdx.x * 32;
    const int h0  = blockIdx.y * 64;

    const int lrA = tid >> 2;           // 0..31 (m row for A load)
    const int kA  = (tid & 3) * 8;      // k sub for A load (8 floats)
    const int lrB = tid >> 1;           // 0..63 (n row for B load)
    const int kB  = (tid & 1) * 16;     // k sub for B load (16 floats)

    const int tx = tid & 15;            // n micro-col
    const int ty = tid >> 4;            // m micro-row (0..7)

    const float* pA = &In[(r0 + lrA) * Fc + kA];
    const float* pB = &W [(h0 + lrB) * Fc + kB];

    ull acc[4][2] = {};

    // prologue: chunk 0 -> buf 0
    {
        float4 a0 = *(const float4*)pA;
        float4 a1 = *(const float4*)(pA + 4);
        #pragma unroll
        for (int j = 0; j < 4; j++) {
            As[0][kA + j][lrA]     = (&a0.x)[j];
            As[0][kA + 4 + j][lrA] = (&a1.x)[j];
        }
        #pragma unroll
        for (int q = 0; q < 4; q++) {
            float4 bv = *(const float4*)(pB + q * 4);
            #pragma unroll
            for (int j = 0; j < 4; j++)
                Bs[0][kB + q * 4 + j][lrB] = (&bv.x)[j];
        }
    }
    __syncthreads();

    int buf = 0;
    for (int k0 = 32; k0 <= Fc; k0 += 32) {
        float4 a0, a1, b0, b1, b2, b3;
        if (k0 < Fc) {
            a0 = *(const float4*)(pA + k0);
            a1 = *(const float4*)(pA + k0 + 4);
            b0 = *(const float4*)(pB + k0);
            b1 = *(const float4*)(pB + k0 + 4);
            b2 = *(const float4*)(pB + k0 + 8);
            b3 = *(const float4*)(pB + k0 + 12);
        }
        #pragma unroll
        for (int kk = 0; kk < 32; kk++) {
            float4 a       = *(const float4*)&As[buf][kk][ty * 4];
            ulonglong2 B01 = *(const ulonglong2*)&Bs[buf][kk][tx * 4];
            ull ax = pack2(a.x, a.x), ay = pack2(a.y, a.y);
            ull az = pack2(a.z, a.z), aw = pack2(a.w, a.w);
            acc[0][0] = fma2(ax, B01.x, acc[0][0]);
            acc[0][1] = fma2(ax, B01.y, acc[0][1]);
            acc[1][0] = fma2(ay, B01.x, acc[1][0]);
            acc[1][1] = fma2(ay, B01.y, acc[1][1]);
            acc[2][0] = fma2(az, B01.x, acc[2][0]);
            acc[2][1] = fma2(az, B01.y, acc[2][1]);
            acc[3][0] = fma2(aw, B01.x, acc[3][0]);
            acc[3][1] = fma2(aw, B01.y, acc[3][1]);
        }
        if (k0 < Fc) {
            int nb = buf ^ 1;
            #pragma unroll
            for (int j = 0; j < 4; j++) {
                As[nb][kA + j][lrA]     = (&a0.x)[j];
                As[nb][kA + 4 + j][lrA] = (&a1.x)[j];
            }
            #pragma unroll
            for (int j = 0; j < 4; j++) {
                Bs[nb][kB + j][lrB]      = (&b0.x)[j];
                Bs[nb][kB + 4 + j][lrB]  = (&b1.x)[j];
                Bs[nb][kB + 8 + j][lrB]  = (&b2.x)[j];
                Bs[nb][kB + 12 + j][lrB] = (&b3.x)[j];
            }
            __syncthreads();
            buf = nb;
        }
    }

    #pragma unroll
    for (int i = 0; i < 4; i++) {
        float2 p0 = unpack2(acc[i][0]);
        float2 p1 = unpack2(acc[i][1]);
        *(float4*)&Out[(r0 + ty * 4 + i) * Hc + h0 + tx * 4] =
            make_float4(p0.x, p0.y, p1.x, p1.y);
    }
}

// ---------------------------------------------------------------------------
// Kernel 2: GEMM-shaped tanh-score (MUFU-bound, at its floor — unchanged).
// S[b,y,l] = sum_h vm[h] * tanh(Xp[b,l,h] - Yp[b,y,h])
// ---------------------------------------------------------------------------
__global__ __launch_bounds__(256) void score_tile_kernel(const float* __restrict__ vm)
{
    const int b  = blockIdx.z;
    const int y0 = blockIdx.y * 64;
    const int l0 = blockIdx.x * 64;

    __shared__ float Ys[16][68];
    __shared__ float Xs[16][68];
    __shared__ float Vs[Hc];

    const int tid = threadIdx.x;
    for (int i = tid; i < Hc; i += 256) Vs[i] = vm[i];

    const int lrow = tid >> 2;
    const int f4   = (tid & 3) * 4;
    const int tx   = tid & 15;
    const int ty   = tid >> 4;

    const float* Yb = g_Yp + (b * LYc + y0) * Hc;
    const float* Xb = g_Xp + (b * LXc + l0) * Hc;

    float acc[4][4] = {};

    for (int k0 = 0; k0 < Hc; k0 += 16) {
        float4 av = *(const float4*)&Yb[lrow * Hc + k0 + f4];
        float4 bv = *(const float4*)&Xb[lrow * Hc + k0 + f4];
        __syncthreads();
        Ys[f4 + 0][lrow] = av.x; Ys[f4 + 1][lrow] = av.y;
        Ys[f4 + 2][lrow] = av.z; Ys[f4 + 3][lrow] = av.w;
        Xs[f4 + 0][lrow] = bv.x; Xs[f4 + 1][lrow] = bv.y;
        Xs[f4 + 2][lrow] = bv.z; Xs[f4 + 3][lrow] = bv.w;
        __syncthreads();

        #pragma unroll
        for (int kk = 0; kk < 16; kk++) {
            const float v = Vs[k0 + kk];
            float4 yv = *(const float4*)&Ys[kk][ty * 4];
            float4 xv = *(const float4*)&Xs[kk][tx * 4];
            float t00 = tanh_fast(xv.x - yv.x);
            float t01 = tanh_fast(xv.y - yv.x);
            float t02 = tanh_fast(xv.z - yv.x);
            float t03 = tanh_fast(xv.w - yv.x);
            float t10 = tanh_fast(xv.x - yv.y);
            float t11 = tanh_fast(xv.y - yv.y);
            float t12 = tanh_fast(xv.z - yv.y);
            float t13 = tanh_fast(xv.w - yv.y);
            float t20 = tanh_fast(xv.x - yv.z);
            float t21 = tanh_fast(xv.y - yv.z);
            float t22 = tanh_fast(xv.z - yv.z);
            float t23 = tanh_fast(xv.w - yv.z);
            float t30 = tanh_fast(xv.x - yv.w);
            float t31 = tanh_fast(xv.y - yv.w);
            float t32 = tanh_fast(xv.z - yv.w);
            float t33 = tanh_fast(xv.w - yv.w);
            acc[0][0] = fmaf(v, t00, acc[0][0]);
            acc[0][1] = fmaf(v, t01, acc[0][1]);
            acc[0][2] = fmaf(v, t02, acc[0][2]);
            acc[0][3] = fmaf(v, t03, acc[0][3]);
            acc[1][0] = fmaf(v, t10, acc[1][0]);
            acc[1][1] = fmaf(v, t11, acc[1][1]);
            acc[1][2] = fmaf(v, t12, acc[1][2]);
            acc[1][3] = fmaf(v, t13, acc[1][3]);
            acc[2][0] = fmaf(v, t20, acc[2][0]);
            acc[2][1] = fmaf(v, t21, acc[2][1]);
            acc[2][2] = fmaf(v, t22, acc[2][2]);
            acc[2][3] = fmaf(v, t23, acc[2][3]);
            acc[3][0] = fmaf(v, t30, acc[3][0]);
            acc[3][1] = fmaf(v, t31, acc[3][1]);
            acc[3][2] = fmaf(v, t32, acc[3][2]);
            acc[3][3] = fmaf(v, t33, acc[3][3]);
        }
    }

    float* Sb = g_S + (b * LYc + y0) * LXc + l0;
    #pragma unroll
    for (int i = 0; i < 4; i++) {
        float4 st = make_float4(acc[i][0], acc[i][1], acc[i][2], acc[i][3]);
        *(float4*)&Sb[(ty * 4 + i) * LXc + tx * 4] = st;
    }
}

// ---------------------------------------------------------------------------
// Kernel 3a: softmax over l, in place on g_S. Warp per row.
// ---------------------------------------------------------------------------
__global__ __launch_bounds__(256) void softmax_kernel()
{
    const int b    = blockIdx.y;
    const int y    = blockIdx.x * 8 + (threadIdx.x >> 5);
    const int lane = threadIdx.x & 31;

    float* Srow = g_S + (b * LYc + y) * LXc;
    float v[12];
    float mx = -1e30f;
    #pragma unroll
    for (int j = 0; j < 12; j++) {
        v[j] = Srow[lane + 32 * j];
        mx = fmaxf(mx, v[j]);
    }
    #pragma unroll
    for (int o = 16; o; o >>= 1)
        mx = fmaxf(mx, __shfl_xor_sync(0xffffffffu, mx, o));
    float sum = 0.f;
    #pragma unroll
    for (int j = 0; j < 12; j++) {
        v[j] = ex2_fast((v[j] - mx) * 1.4426950408889634f);
        sum += v[j];
    }
    #pragma unroll
    for (int o = 16; o; o >>= 1)
        sum += __shfl_xor_sync(0xffffffffu, sum, o);
    float inv = 1.0f / sum;
    #pragma unroll
    for (int j = 0; j < 12; j++)
        Srow[lane + 32 * j] = v[j] * inv;
}

// ---------------------------------------------------------------------------
// Kernel 3b: qtm[b,y,f] = sum_l A[b,y,l] * x[b,l,f]
// Per-batch GEMM M=384(y), N=512(f), K=384(l).  32x64 tile, 128 threads,
// 4x4 micro (R5 tiling), BK=32 double-buffered (12 chunks).
// grid (8, 12, 4) = 384 blocks.
// ---------------------------------------------------------------------------
__global__ __launch_bounds__(128) void outgemm_kernel(
    const float* __restrict__ x, float* __restrict__ out)
{
    const int b  = blockIdx.z;
    const int f0 = blockIdx.x * 64;
    const int y0 = blockIdx.y * 32;

    __shared__ float As[2][32][36];   // [k(l)][y(32)]
    __shared__ float Xs[2][32][68];   // [k(l)][f(64)]

    const int tid = threadIdx.x;

    const int lrA = tid >> 2;           // 0..31 (y row for A load)
    const int kA  = (tid & 3) * 8;      // l sub for A load (8 floats)
    const int lX  = tid >> 2;           // 0..31 (l row for X load)
    const int fX  = (tid & 3) * 16;     // f sub for X load (16 floats)

    const int tx = tid & 15;            // f micro-col
    const int ty = tid >> 4;            // y micro-row (0..7)

    const float* pA = g_S + (b * LYc + y0 + lrA) * LXc + kA;
    const float* pX = x + b * LXc * Fc + lX * Fc + f0 + fX;

    ull acc[4][2] = {};

    {
        float4 a0 = *(const float4*)pA;
        float4 a1 = *(const float4*)(pA + 4);
        #pragma unroll
        for (int j = 0; j < 4; j++) {
            As[0][kA + j][lrA]     = (&a0.x)[j];
            As[0][kA + 4 + j][lrA] = (&a1.x)[j];
        }
        #pragma unroll
        for (int q = 0; q < 4; q++)
            *(float4*)&Xs[0][lX][fX + q * 4] = *(const float4*)(pX + q * 4);
    }
    __syncthreads();

    int buf = 0;
    for (int k0 = 32; k0 <= LXc; k0 += 32) {
        float4 a0, a1, x0, x1, x2, x3;
        if (k0 < LXc) {
            a0 = *(const float4*)(pA + k0);
            a1 = *(const float4*)(pA + k0 + 4);
            x0 = *(const float4*)(pX + k0 * Fc);
            x1 = *(const float4*)(pX + k0 * Fc + 4);
            x2 = *(const float4*)(pX + k0 * Fc + 8);
            x3 = *(const float4*)(pX + k0 * Fc + 12);
        }
        #pragma unroll
        for (int kk = 0; kk < 32; kk++) {
            float4 a       = *(const float4*)&As[buf][kk][ty * 4];
            ulonglong2 B01 = *(const ulonglong2*)&Xs[buf][kk][tx * 4];
            ull ax = pack2(a.x, a.x), ay = pack2(a.y, a.y);
            ull az = pack2(a.z, a.z), aw = pack2(a.w, a.w);
            acc[0][0] = fma2(ax, B01.x, acc[0][0]);
            acc[0][1] = fma2(ax, B01.y, acc[0][1]);
            acc[1][0] = fma2(ay, B01.x, acc[1][0]);
            acc[1][1] = fma2(ay, B01.y, acc[1][1]);
            acc[2][0] = fma2(az, B01.x, acc[2][0]);
            acc[2][1] = fma2(az, B01.y, acc[2][1]);
            acc[3][0] = fma2(aw, B01.x, acc[3][0]);
            acc[3][1] = fma2(aw, B01.y, acc[3][1]);
        }
        if (k0 < LXc) {
            int nb = buf ^ 1;
            #pragma unroll
            for (int j = 0; j < 4; j++) {
                As[nb][kA + j][lrA]     = (&a0.x)[j];
                As[nb][kA + 4 + j][lrA] = (&a1.x)[j];
            }
            *(float4*)&Xs[nb][lX][fX]      = x0;
            *(float4*)&Xs[nb][lX][fX + 4]  = x1;
            *(float4*)&Xs[nb][lX][fX + 8]  = x2;
            *(float4*)&Xs[nb][lX][fX + 12] = x3;
            __syncthreads();
            buf = nb;
        }
    }

    #pragma unroll
    for (int i = 0; i < 4; i++) {
        float2 p0 = unpack2(acc[i][0]);
        float2 p1 = unpack2(acc[i][1]);
        *(float4*)&out[(b * LYc + y0 + ty * 4 + i) * Fc + f0 + tx * 4] =
            make_float4(p0.x, p0.y, p1.x, p1.y);
    }
}

// ---------------------------------------------------------------------------
extern "C" void kernel_launch(void* const* d_in, const int* in_sizes, int n_in,
                              void* d_out, int out_size)
{
    const float* x  = (const float*)d_in[0];
    const float* y  = (const float*)d_in[1];
    const float* Wm = (const float*)d_in[2];
    const float* vm = (const float*)d_in[3];
    float* out = (float*)d_out;

    proj_kernel      <<<dim3(LXc * Bc / 32, Hc / 64, 2), 128>>>(x, y, Wm);
    score_tile_kernel<<<dim3(LXc / 64, LYc / 64, Bc), 256>>>(vm);
    softmax_kernel   <<<dim3(LYc / 8, Bc), 256>>>();
    outgemm_kernel   <<<dim3(Fc / 64, LYc / 32, Bc), 128>>>(x, out);
}

// round 12
// speedup vs baseline: 1.5581x; 1.2601x over previous
#include <cuda_runtime.h>
#include <cuda_bf16.h>
#include <cstdint>

#define Bc  4
#define LXc 384
#define LYc 384
#define Hc  256
#define Fc  512

// scratch (allocation-free rule: __device__ globals)
__device__ float g_Xp[Bc * LXc * Hc];   // x @ Wm^T
__device__ float g_Yp[Bc * LYc * Hc];   // y @ Wm^T
__device__ float g_S [Bc * LYc * LXc];  // scores -> softmax'd in place
__device__ float g_xT[Bc * Fc * LXc];   // x transposed: [b][f][l]

__device__ __forceinline__ float tanh_fast(float x) {
    float r; asm("tanh.approx.f32 %0, %1;" : "=f"(r) : "f"(x)); return r;
}
__device__ __forceinline__ float ex2_fast(float x) {
    float r; asm("ex2.approx.f32 %0, %1;" : "=f"(r) : "f"(x)); return r;
}
__device__ __forceinline__ uint32_t smem_u32(const void* p) {
    uint32_t a;
    asm("{ .reg .u64 t; cvta.to.shared.u64 t, %1; cvt.u32.u64 %0, t; }"
        : "=r"(a) : "l"(p));
    return a;
}
// pack 2 fp32 -> bf16x2 (lo in low half)
__device__ __forceinline__ uint32_t packbf(float lo, float hi) {
    uint32_t r;
    asm("cvt.rn.bf16x2.f32 %0, %1, %2;" : "=r"(r) : "f"(hi), "f"(lo));
    return r;
}
// residual lo-part of a hi-packed pair
__device__ __forceinline__ uint32_t packres(uint32_t h, float lo, float hi) {
    float fl = __uint_as_float(h << 16);
    float fh = __uint_as_float(h & 0xffff0000u);
    return packbf(lo - fl, hi - fh);
}
__device__ __forceinline__ void ldm4(uint32_t* r, uint32_t a) {
    asm volatile("ldmatrix.sync.aligned.m8n8.x4.shared.b16 {%0,%1,%2,%3}, [%4];"
                 : "=r"(r[0]), "=r"(r[1]), "=r"(r[2]), "=r"(r[3]) : "r"(a));
}
__device__ __forceinline__ void mma16816(float* c, const uint32_t* a,
                                         uint32_t b0, uint32_t b1) {
    asm volatile(
        "mma.sync.aligned.m16n8k16.row.col.f32.bf16.bf16.f32 "
        "{%0,%1,%2,%3}, {%4,%5,%6,%7}, {%8,%9}, {%0,%1,%2,%3};"
        : "+f"(c[0]), "+f"(c[1]), "+f"(c[2]), "+f"(c[3])
        : "r"(a[0]), "r"(a[1]), "r"(a[2]), "r"(a[3]), "r"(b0), "r"(b1));
}

// ---------------------------------------------------------------------------
// Tensor-core GEMM (HMMA): C[64,64] = A[64,K] @ B[64,K]^T, fp32 in/out,
// bf16 hi/lo 3-product split, fp32 accum.  128 threads (4 warps, 32x32 each).
// K multiple of 32. smem rows padded to 40 ushort (80B: 16B-aligned,
// conflict-free for ldmatrix 8-row phases).
// ---------------------------------------------------------------------------
__device__ void gemm_mma(const float* __restrict__ A, int lda,
                         const float* __restrict__ B, int ldb,
                         float* __restrict__ C, int ldc, int K)
{
    __shared__ __align__(16) ushort AH[2][64 * 40], AL[2][64 * 40];
    __shared__ __align__(16) ushort BH[2][64 * 40], BL[2][64 * 40];

    const int tid = threadIdx.x, wid = tid >> 5, lane = tid & 31;
    const int wm = (wid >> 1) * 32, wn = (wid & 1) * 32;

    const int crow = tid >> 1;          // conversion row 0..63
    const int ckb  = (tid & 1) * 16;    // conversion k offset (16 floats)
    const int cidx = crow * 40 + ckb;

    const float* pA = A + crow * lda + ckb;
    const float* pB = B + crow * ldb + ckb;

    float c[2][4][4];
    #pragma unroll
    for (int i = 0; i < 2; i++)
        #pragma unroll
        for (int j = 0; j < 4; j++)
            #pragma unroll
            for (int q = 0; q < 4; q++) c[i][j][q] = 0.f;

    auto conv = [&](ushort* Hs, ushort* Ls,
                    float4 v0, float4 v1, float4 v2, float4 v3) {
        uint32_t h0 = packbf(v0.x, v0.y), h1 = packbf(v0.z, v0.w);
        uint32_t h2 = packbf(v1.x, v1.y), h3 = packbf(v1.z, v1.w);
        uint32_t h4 = packbf(v2.x, v2.y), h5 = packbf(v2.z, v2.w);
        uint32_t h6 = packbf(v3.x, v3.y), h7 = packbf(v3.z, v3.w);
        *(uint4*)&Hs[cidx]     = make_uint4(h0, h1, h2, h3);
        *(uint4*)&Hs[cidx + 8] = make_uint4(h4, h5, h6, h7);
        uint32_t l0 = packres(h0, v0.x, v0.y), l1 = packres(h1, v0.z, v0.w);
        uint32_t l2 = packres(h2, v1.x, v1.y), l3 = packres(h3, v1.z, v1.w);
        uint32_t l4 = packres(h4, v2.x, v2.y), l5 = packres(h5, v2.z, v2.w);
        uint32_t l6 = packres(h6, v3.x, v3.y), l7 = packres(h7, v3.z, v3.w);
        *(uint4*)&Ls[cidx]     = make_uint4(l0, l1, l2, l3);
        *(uint4*)&Ls[cidx + 8] = make_uint4(l4, l5, l6, l7);
    };

    // prologue: chunk 0 -> buf 0
    conv(AH[0], AL[0],
         *(const float4*)pA, *(const float4*)(pA + 4),
         *(const float4*)(pA + 8), *(const float4*)(pA + 12));
    conv(BH[0], BL[0],
         *(const float4*)pB, *(const float4*)(pB + 4),
         *(const float4*)(pB + 8), *(const float4*)(pB + 12));
    __syncthreads();

    const int nch = K >> 5;
    int buf = 0;
    for (int ch = 0; ch < nch; ch++) {
        float4 a0, a1, a2, a3, b0, b1, b2, b3;
        if (ch + 1 < nch) {
            const int nk = (ch + 1) * 32;
            a0 = *(const float4*)(pA + nk);      a1 = *(const float4*)(pA + nk + 4);
            a2 = *(const float4*)(pA + nk + 8);  a3 = *(const float4*)(pA + nk + 12);
            b0 = *(const float4*)(pB + nk);      b1 = *(const float4*)(pB + nk + 4);
            b2 = *(const float4*)(pB + nk + 8);  b3 = *(const float4*)(pB + nk + 12);
        }

        #pragma unroll
        for (int ks = 0; ks < 2; ks++) {
            uint32_t aHf[2][4], aLf[2][4], bHf[2][4], bLf[2][4];
            #pragma unroll
            for (int mt = 0; mt < 2; mt++) {
                const int row = wm + mt * 16 + (lane & 15);
                const int kc  = ks * 16 + (lane >> 4) * 8;
                const int off = row * 40 + kc;
                ldm4(aHf[mt], smem_u32(&AH[buf][off]));
                ldm4(aLf[mt], smem_u32(&AL[buf][off]));
            }
            #pragma unroll
            for (int g = 0; g < 2; g++) {
                const int row = wn + g * 16 + ((lane >> 4) << 3) + (lane & 7);
                const int kc  = ks * 16 + ((lane >> 3) & 1) * 8;
                const int off = row * 40 + kc;
                ldm4(bHf[g], smem_u32(&BH[buf][off]));
                ldm4(bLf[g], smem_u32(&BL[buf][off]));
            }
            #pragma unroll
            for (int mt = 0; mt < 2; mt++)
                #pragma unroll
                for (int g = 0; g < 2; g++)
                    #pragma unroll
                    for (int h = 0; h < 2; h++) {
                        float* cf = c[mt][g * 2 + h];
                        mma16816(cf, aHf[mt], bHf[g][2*h], bHf[g][2*h+1]);
                        mma16816(cf, aLf[mt], bHf[g][2*h], bHf[g][2*h+1]);
                        mma16816(cf, aHf[mt], bLf[g][2*h], bLf[g][2*h+1]);
                    }
        }

        if (ch + 1 < nch) {
            const int nb = buf ^ 1;
            conv(AH[nb], AL[nb], a0, a1, a2, a3);
            conv(BH[nb], BL[nb], b0, b1, b2, b3);
            __syncthreads();
            buf = nb;
        }
    }

    // epilogue
    #pragma unroll
    for (int mt = 0; mt < 2; mt++) {
        const int r0 = wm + mt * 16 + (lane >> 2);
        #pragma unroll
        for (int nt = 0; nt < 4; nt++) {
            const int cc = wn + nt * 8 + (lane & 3) * 2;
            float* p = C + r0 * ldc + cc;
            *(float2*)p             = make_float2(c[mt][nt][0], c[mt][nt][1]);
            *(float2*)(p + 8 * ldc) = make_float2(c[mt][nt][2], c[mt][nt][3]);
        }
    }
}

// ---------------------------------------------------------------------------
// Kernel 0: transpose x -> g_xT[b][f][l]
// ---------------------------------------------------------------------------
__global__ __launch_bounds__(256) void transpose_x_kernel(const float* __restrict__ x)
{
    __shared__ float t[32][33];
    const int b  = blockIdx.z;
    const int f0 = blockIdx.x * 32;
    const int l0 = blockIdx.y * 32;
    const int tx = threadIdx.x & 31;
    const int ty = threadIdx.x >> 5;

    #pragma unroll
    for (int i = ty; i < 32; i += 8)
        t[i][tx] = x[(b * LXc + l0 + i) * Fc + f0 + tx];
    __syncthreads();
    #pragma unroll
    for (int i = ty; i < 32; i += 8)
        g_xT[(b * Fc + f0 + i) * LXc + l0 + tx] = t[tx][i];
}

// ---------------------------------------------------------------------------
// Kernel 1: proj.  Out[r,h] = sum_f In[r,f]*W[h,f].  K=512.
// grid (Hc/64=4, 1536/64=24, 2)
// ---------------------------------------------------------------------------
__global__ __launch_bounds__(128) void proj_mma_kernel(
    const float* __restrict__ xin, const float* __restrict__ yin,
    const float* __restrict__ W)
{
    const float* In  = blockIdx.z ? yin  : xin;
    float*       Out = blockIdx.z ? g_Yp : g_Xp;
    gemm_mma(In + blockIdx.y * 64 * Fc, Fc,
             W  + blockIdx.x * 64 * Fc, Fc,
             Out + blockIdx.y * 64 * Hc + blockIdx.x * 64, Hc, Fc);
}

// ---------------------------------------------------------------------------
// Kernel 4: outgemm.  qtm[b,y,f] = sum_l A[b,y,l]*xT[b,f,l].  K=384.
// grid (Fc/64=8, LYc/64=6, Bc)
// ---------------------------------------------------------------------------
__global__ __launch_bounds__(128) void outgemm_mma_kernel(float* __restrict__ out)
{
    const int b = blockIdx.z;
    gemm_mma(g_S  + (b * LYc + blockIdx.y * 64) * LXc, LXc,
             g_xT + (b * Fc  + blockIdx.x * 64) * LXc, LXc,
             out  + (b * LYc + blockIdx.y * 64) * Fc + blockIdx.x * 64,
             Fc, LXc);
}

// ---------------------------------------------------------------------------
// Kernel 2: GEMM-shaped tanh-score (MUFU-bound, at its floor — unchanged).
// ---------------------------------------------------------------------------
__global__ __launch_bounds__(256) void score_tile_kernel(const float* __restrict__ vm)
{
    const int b  = blockIdx.z;
    const int y0 = blockIdx.y * 64;
    const int l0 = blockIdx.x * 64;

    __shared__ float Ys[16][68];
    __shared__ float Xs[16][68];
    __shared__ float Vs[Hc];

    const int tid = threadIdx.x;
    for (int i = tid; i < Hc; i += 256) Vs[i] = vm[i];

    const int lrow = tid >> 2;
    const int f4   = (tid & 3) * 4;
    const int tx   = tid & 15;
    const int ty   = tid >> 4;

    const float* Yb = g_Yp + (b * LYc + y0) * Hc;
    const float* Xb = g_Xp + (b * LXc + l0) * Hc;

    float acc[4][4] = {};

    for (int k0 = 0; k0 < Hc; k0 += 16) {
        float4 av = *(const float4*)&Yb[lrow * Hc + k0 + f4];
        float4 bv = *(const float4*)&Xb[lrow * Hc + k0 + f4];
        __syncthreads();
        Ys[f4 + 0][lrow] = av.x; Ys[f4 + 1][lrow] = av.y;
        Ys[f4 + 2][lrow] = av.z; Ys[f4 + 3][lrow] = av.w;
        Xs[f4 + 0][lrow] = bv.x; Xs[f4 + 1][lrow] = bv.y;
        Xs[f4 + 2][lrow] = bv.z; Xs[f4 + 3][lrow] = bv.w;
        __syncthreads();

        #pragma unroll
        for (int kk = 0; kk < 16; kk++) {
            const float v = Vs[k0 + kk];
            float4 yv = *(const float4*)&Ys[kk][ty * 4];
            float4 xv = *(const float4*)&Xs[kk][tx * 4];
            float t00 = tanh_fast(xv.x - yv.x);
            float t01 = tanh_fast(xv.y - yv.x);
            float t02 = tanh_fast(xv.z - yv.x);
            float t03 = tanh_fast(xv.w - yv.x);
            float t10 = tanh_fast(xv.x - yv.y);
            float t11 = tanh_fast(xv.y - yv.y);
            float t12 = tanh_fast(xv.z - yv.y);
            float t13 = tanh_fast(xv.w - yv.y);
            float t20 = tanh_fast(xv.x - yv.z);
            float t21 = tanh_fast(xv.y - yv.z);
            float t22 = tanh_fast(xv.z - yv.z);
            float t23 = tanh_fast(xv.w - yv.z);
            float t30 = tanh_fast(xv.x - yv.w);
            float t31 = tanh_fast(xv.y - yv.w);
            float t32 = tanh_fast(xv.z - yv.w);
            float t33 = tanh_fast(xv.w - yv.w);
            acc[0][0] = fmaf(v, t00, acc[0][0]);
            acc[0][1] = fmaf(v, t01, acc[0][1]);
            acc[0][2] = fmaf(v, t02, acc[0][2]);
            acc[0][3] = fmaf(v, t03, acc[0][3]);
            acc[1][0] = fmaf(v, t10, acc[1][0]);
            acc[1][1] = fmaf(v, t11, acc[1][1]);
            acc[1][2] = fmaf(v, t12, acc[1][2]);
            acc[1][3] = fmaf(v, t13, acc[1][3]);
            acc[2][0] = fmaf(v, t20, acc[2][0]);
            acc[2][1] = fmaf(v, t21, acc[2][1]);
            acc[2][2] = fmaf(v, t22, acc[2][2]);
            acc[2][3] = fmaf(v, t23, acc[2][3]);
            acc[3][0] = fmaf(v, t30, acc[3][0]);
            acc[3][1] = fmaf(v, t31, acc[3][1]);
            acc[3][2] = fmaf(v, t32, acc[3][2]);
            acc[3][3] = fmaf(v, t33, acc[3][3]);
        }
    }

    float* Sb = g_S + (b * LYc + y0) * LXc + l0;
    #pragma unroll
    for (int i = 0; i < 4; i++) {
        float4 st = make_float4(acc[i][0], acc[i][1], acc[i][2], acc[i][3]);
        *(float4*)&Sb[(ty * 4 + i) * LXc + tx * 4] = st;
    }
}

// ---------------------------------------------------------------------------
// Kernel 3: softmax over l, in place on g_S. Warp per row.
// ---------------------------------------------------------------------------
__global__ __launch_bounds__(256) void softmax_kernel()
{
    const int b    = blockIdx.y;
    const int y    = blockIdx.x * 8 + (threadIdx.x >> 5);
    const int lane = threadIdx.x & 31;

    float* Srow = g_S + (b * LYc + y) * LXc;
    float v[12];
    float mx = -1e30f;
    #pragma unroll
    for (int j = 0; j < 12; j++) {
        v[j] = Srow[lane + 32 * j];
        mx = fmaxf(mx, v[j]);
    }
    #pragma unroll
    for (int o = 16; o; o >>= 1)
        mx = fmaxf(mx, __shfl_xor_sync(0xffffffffu, mx, o));
    float sum = 0.f;
    #pragma unroll
    for (int j = 0; j < 12; j++) {
        v[j] = ex2_fast((v[j] - mx) * 1.4426950408889634f);
        sum += v[j];
    }
    #pragma unroll
    for (int o = 16; o; o >>= 1)
        sum += __shfl_xor_sync(0xffffffffu, sum, o);
    float inv = 1.0f / sum;
    #pragma unroll
    for (int j = 0; j < 12; j++)
        Srow[lane + 32 * j] = v[j] * inv;
}

// ---------------------------------------------------------------------------
extern "C" void kernel_launch(void* const* d_in, const int* in_sizes, int n_in,
                              void* d_out, int out_size)
{
    const float* x  = (const float*)d_in[0];
    const float* y  = (const float*)d_in[1];
    const float* Wm = (const float*)d_in[2];
    const float* vm = (const float*)d_in[3];
    float* out = (float*)d_out;

    transpose_x_kernel<<<dim3(Fc / 32, LXc / 32, Bc), 256>>>(x);
    proj_mma_kernel   <<<dim3(Hc / 64, (LXc * Bc) / 64, 2), 128>>>(x, y, Wm);
    score_tile_kernel <<<dim3(LXc / 64, LYc / 64, Bc), 256>>>(vm);
    softmax_kernel    <<<dim3(LYc / 8, Bc), 256>>>();
    outgemm_mma_kernel<<<dim3(Fc / 64, LYc / 64, Bc), 128>>>(out);
}